// round 16
// baseline (speedup 1.0000x reference)
#include <cuda_runtime.h>

// SSIM loss: 1 - mean(ssim_map(clean, adv)), 11x11 gaussian sigma=1.5, zero SAME padding.
// d_in[0]=clean [32,3,512,512] f32, d_in[1]=adversarial. Output: 1 float.
//
// 32x40 output tile (50x42 halo), 320-thread blocks, 4 blocks/SM = 40 warps/SM.
// Last grid row is a 32x32 instantiation (512 = 12*40 + 32).
// Horizontal: 2 adjacent outputs/task via ld.shared.v2.u64, incremental
// constant-offset addressing. Vertical: 4 consecutive output rows/thread.

#define IMG 512
#define HALO 5
#define EXT_X 42
#define NTHR 320
#define NPIX (32.0 * 3.0 * 512.0 * 512.0)
#define NBLOCKS (16 * 13 * 96)

typedef unsigned long long u64;

__device__ double g_ssim_acc = 0.0;
__device__ unsigned int g_done = 0;

__device__ __forceinline__ u64 pack2(float x, float y) {
    u64 r; asm("mov.b64 %0, {%1, %2};" : "=l"(r) : "f"(x), "f"(y)); return r;
}
__device__ __forceinline__ float2 un2(u64 v) {
    float2 r; asm("mov.b64 {%0, %1}, %2;" : "=f"(r.x), "=f"(r.y) : "l"(v)); return r;
}
__device__ __forceinline__ u64 fma2(u64 a, u64 b, u64 c) {
    u64 d; asm("fma.rn.f32x2 %0, %1, %2, %3;" : "=l"(d) : "l"(a), "l"(b), "l"(c)); return d;
}
__device__ __forceinline__ u64 mul2(u64 a, u64 b) {
    u64 d; asm("mul.rn.f32x2 %0, %1, %2;" : "=l"(d) : "l"(a), "l"(b)); return d;
}
__device__ __forceinline__ unsigned saddr(const void* p) {
    return (unsigned)__cvta_generic_to_shared(p);
}
__device__ __forceinline__ void lds_v2u64(u64& a, u64& b, unsigned addr) {
    asm("ld.shared.v2.u64 {%0, %1}, [%2];" : "=l"(a), "=l"(b) : "r"(addr));
}
__device__ __forceinline__ void sts_v2u64(unsigned addr, u64 a, u64 b) {
    asm volatile("st.shared.v2.u64 [%0], {%1, %2};" :: "r"(addr), "l"(a), "l"(b));
}
__device__ __forceinline__ void sts_v2f32(unsigned addr, float a, float b) {
    asm volatile("st.shared.v2.f32 [%0], {%1, %2};" :: "r"(addr), "f"(a), "f"(b));
}

#define W0 0.26601173f
#define W1 0.21300555f
#define W2 0.10936069f
#define W3 0.03600077f
#define W4 0.00759875f
#define W5 0.00102838f

template<int TY>
struct SmemT {
    u64   ca[TY + 10][EXT_X];   // packed (x,y); row stride 336B (16B aligned)
    u64   mu[TY + 10][32];
    u64   sq[TY + 10][32];
    float xx[TY + 10][32];
};
#define SMEM_BYTES ((int)sizeof(SmemT<40>))

template<int TY>
__device__ __forceinline__ float ssim_tile(
    char* smem_raw, const float* __restrict__ cp, const float* __restrict__ ap,
    int x0, int y0)
{
    constexpr int EY = TY + 10;
    constexpr int ITERH = (EY * 16 + NTHR - 1) / NTHR;
    constexpr int RSTEP = NTHR / 16;           // rows per horizontal iteration (20)
    SmemT<TY>* sm = reinterpret_cast<SmemT<TY>*>(smem_raw);

    const float wf[11] = {W5, W4, W3, W2, W1, W0, W1, W2, W3, W4, W5};
    const u64 p0 = pack2(W0, W0), p1 = pack2(W1, W1), p2 = pack2(W2, W2);
    const u64 p3 = pack2(W3, W3), p4 = pack2(W4, W4), p5 = pack2(W5, W5);
    const u64 wp[11] = {p5, p4, p3, p2, p1, p0, p1, p2, p3, p4, p5};

    const int tid = threadIdx.x;
    const int tx = tid & 31;
    const int ty = tid >> 5;

    // ---- load EYx42 halo tile (zero padding), incremental (r,c) walker ----
    {
        int r = tid / EXT_X;
        int c = tid - r * EXT_X;
        constexpr int ITER = (EY * EXT_X + NTHR - 1) / NTHR;
        #pragma unroll
        for (int it = 0; it < ITER; it++) {
            if (it < ITER - 1 || r < EY) {
                int gy = y0 - HALO + r;
                int gx = x0 - HALO + c;
                float cv = 0.f, av = 0.f;
                if ((unsigned)gy < IMG && (unsigned)gx < IMG) {
                    cv = cp[gy * IMG + gx];
                    av = ap[gy * IMG + gx];
                }
                sm->ca[r][c] = pack2(cv, av);
            }
            r += 7; c += 26;                  // 320 = 7*42 + 26
            if (c >= EXT_X) { c -= EXT_X; r += 1; }
        }
    }
    __syncthreads();

    // ---- horizontal pass: EY x 16 column-pair tasks.
    //      Incremental addressing: idx += 320 <=> r += 20 (const offsets). ----
    {
        const int r0 = tid >> 4;              // 0..19
        const int c0 = (tid & 15) << 1;
        unsigned a_ca = saddr(&sm->ca[r0][c0]);
        unsigned a_mu = saddr(&sm->mu[r0][c0]);
        unsigned a_sq = saddr(&sm->sq[r0][c0]);
        unsigned a_xx = saddr(&sm->xx[r0][c0]);

        #pragma unroll
        for (int it = 0; it < ITERH; it++) {
            if (it < ITERH - 1 || r0 + RSTEP * it < EY) {
                u64 v[12];
                #pragma unroll
                for (int i = 0; i < 6; i++)
                    lds_v2u64(v[2 * i], v[2 * i + 1], a_ca + 16 * i);

                u64 ma = 0ull, sa = 0ull, mb = 0ull, sb = 0ull;
                float xa = 0.f, xb = 0.f;
                #pragma unroll
                for (int k = 0; k < 12; k++) {
                    u64 vs = mul2(v[k], v[k]);     // (x^2, y^2), shared
                    float2 h = un2(v[k]);          // register-pair halves
                    float xy = h.x * h.y;          // shared
                    if (k <= 10) {
                        ma = fma2(wp[k], v[k], ma);
                        sa = fma2(wp[k], vs, sa);
                        xa = fmaf(wf[k], xy, xa);
                    }
                    if (k >= 1) {
                        mb = fma2(wp[k - 1], v[k], mb);
                        sb = fma2(wp[k - 1], vs, sb);
                        xb = fmaf(wf[k - 1], xy, xb);
                    }
                }
                sts_v2u64(a_mu, ma, mb);
                sts_v2u64(a_sq, sa, sb);
                sts_v2f32(a_xx, xa, xb);
            }
            a_ca += RSTEP * EXT_X * 8;        // +6720
            a_mu += RSTEP * 32 * 8;           // +5120
            a_sq += RSTEP * 32 * 8;           // +5120
            a_xx += RSTEP * 32 * 4;           // +2560
        }
    }
    __syncthreads();

    // ---- vertical pass: 4 consecutive output rows/thread ----
    float local = 0.f;
    if (ty * 4 < TY) {
        const float C1 = 1.0e-4f;
        const float C2 = 9.0e-4f;
        const int rbase = ty * 4;

        u64 am[4] = {0ull, 0ull, 0ull, 0ull};
        u64 ae[4] = {0ull, 0ull, 0ull, 0ull};
        float a12[4] = {0.f, 0.f, 0.f, 0.f};

        #pragma unroll
        for (int j = 0; j < 15; j++) {
            int r = rbase + j;
            u64 mu = sm->mu[r][tx];
            u64 sq = sm->sq[r][tx];
            float xx = sm->xx[r][tx];
            #pragma unroll
            for (int o = 0; o < 4; o++) {
                const int k = j - o;
                if (k >= 0 && k <= 10) {
                    am[o] = fma2(wp[k], mu, am[o]);
                    ae[o] = fma2(wp[k], sq, ae[o]);
                    a12[o] = fmaf(wf[k], xx, a12[o]);
                }
            }
        }

        #pragma unroll
        for (int o = 0; o < 4; o++) {
            float2 m = un2(am[o]);
            float2 e = un2(ae[o]);
            float mu1_sq = m.x * m.x;
            float mu2_sq = m.y * m.y;
            float mu12   = m.x * m.y;
            float sig1  = e.x - mu1_sq;
            float sig2  = e.y - mu2_sq;
            float sig12 = a12[o] - mu12;
            float num = (2.f * mu12 + C1) * (2.f * sig12 + C2);
            float den = (mu1_sq + mu2_sq + C1) * (sig1 + sig2 + C2);
            local += __fdividef(num, den);
        }
    }
    return local;
}

__global__ void __launch_bounds__(NTHR, 4) ssim_kernel(
    const float* __restrict__ clean, const float* __restrict__ adv,
    float* __restrict__ out)
{
    extern __shared__ __align__(16) char smem_raw[];
    __shared__ float s_red[10];

    const int plane = blockIdx.z;
    const float* cp = clean + (size_t)plane * IMG * IMG;
    const float* ap = adv   + (size_t)plane * IMG * IMG;
    const int x0 = blockIdx.x * 32;
    const int tid = threadIdx.x;
    const int tx = tid & 31;
    const int ty = tid >> 5;

    float local;
    if (blockIdx.y < 12)
        local = ssim_tile<40>(smem_raw, cp, ap, x0, blockIdx.y * 40);
    else
        local = ssim_tile<32>(smem_raw, cp, ap, x0, 480);

    // ---- block reduction + fused finalize ----
    #pragma unroll
    for (int off = 16; off > 0; off >>= 1)
        local += __shfl_down_sync(0xFFFFFFFFu, local, off);
    if (tx == 0) s_red[ty] = local;
    __syncthreads();
    if (tid == 0) {
        float bs = 0.f;
        #pragma unroll
        for (int i = 0; i < 10; i++) bs += s_red[i];
        atomicAdd(&g_ssim_acc, (double)bs);
        __threadfence();
        unsigned t = atomicAdd(&g_done, 1u);
        if (t == NBLOCKS - 1) {
            double acc = atomicAdd(&g_ssim_acc, 0.0);
            out[0] = 1.0f - (float)(acc / NPIX);
            g_done = 0;
            g_ssim_acc = 0.0;
        }
    }
}

extern "C" void kernel_launch(void* const* d_in, const int* in_sizes, int n_in,
                              void* d_out, int out_size) {
    const float* clean = (const float*)d_in[0];
    const float* adv   = (const float*)d_in[1];
    float* out = (float*)d_out;

    cudaFuncSetAttribute(ssim_kernel,
                         cudaFuncAttributeMaxDynamicSharedMemorySize, SMEM_BYTES);

    dim3 grid(IMG / 32, 13, 96);   // 16 x 13 x 96 = 19968 blocks
    ssim_kernel<<<grid, NTHR, SMEM_BYTES>>>(clean, adv, out);
}